// round 15
// baseline (speedup 1.0000x reference)
#include <cuda_runtime.h>
#include <cuda_bf16.h>
#include <cstdint>
#include <cstddef>

#define M_NODES 100000
#define N_EDG   1600000
#define SCAN_B 98   // ceil(M_NODES / 1024)

// ---------------- scratch (static device globals; no allocation) ----------------
__device__ int   g_deg[M_NODES];
__device__ int   g_fill[M_NODES];
__device__ int   g_rptr[M_NODES + 1];
__device__ int   g_bsum[SCAN_B];
__device__ int   g_boff[SCAN_B + 1];
__device__ int   g_src[N_EDG];
__device__ float g_w[N_EDG];
__device__ float g_dis[M_NODES];
__device__ __align__(16) float g_bufA[(size_t)M_NODES * 128];
__device__ __align__(16) float g_bufB[(size_t)M_NODES * 128];
__device__ __align__(16) float g_bufC[(size_t)M_NODES * 128];
__device__ __align__(16) float g_bufD[(size_t)M_NODES * 128];
__device__ __align__(16) float g_bufE[(size_t)M_NODES * 128];
// bf16 hi/lo split buffers: GEMM input activations + all weights
__device__ __align__(16) __nv_bfloat16 g_hh[(size_t)M_NODES * 128];
__device__ __align__(16) __nv_bfloat16 g_hl[(size_t)M_NODES * 128];
#define WOFF1 0
#define WOFF2 65536            // 4*128*128
#define WOFF3 98304            // + 4*64*128
#define WTOT  102400           // + 4*16*64
__device__ __align__(16) __nv_bfloat16 g_wh[WTOT];
__device__ __align__(16) __nv_bfloat16 g_wl[WTOT];

// ---------------- threefry2x32 ----------------
__host__ __device__ __forceinline__ unsigned tf_rotl(unsigned x, int r) {
  return (x << r) | (x >> (32 - r));
}

__host__ __device__ __forceinline__ void threefry2x32(
    unsigned k0, unsigned k1, unsigned x0, unsigned x1,
    unsigned& o0, unsigned& o1) {
  unsigned ks2 = k0 ^ k1 ^ 0x1BD11BDAu;
  x0 += k0; x1 += k1;
#define TF_R(r) { x0 += x1; x1 = tf_rotl(x1, (r)); x1 ^= x0; }
  TF_R(13) TF_R(15) TF_R(26) TF_R(6)
  x0 += k1;  x1 += ks2 + 1u;
  TF_R(17) TF_R(29) TF_R(16) TF_R(24)
  x0 += ks2; x1 += k0 + 2u;
  TF_R(13) TF_R(15) TF_R(26) TF_R(6)
  x0 += k0;  x1 += k1 + 3u;
  TF_R(17) TF_R(29) TF_R(16) TF_R(24)
  x0 += k1;  x1 += ks2 + 4u;
  TF_R(13) TF_R(15) TF_R(26) TF_R(6)
  x0 += ks2; x1 += k0 + 5u;
#undef TF_R
  o0 = x0; o1 = x1;
}

// ---------------- warp-MMA helpers (baseline PTX, no 'a'-gated features) --------
__device__ __forceinline__ uint32_t smem_u32(const void* p) {
  uint32_t a;
  asm("{ .reg .u64 t; cvta.to.shared.u64 t, %1; cvt.u32.u64 %0, t; }"
      : "=r"(a) : "l"(p));
  return a;
}

__device__ __forceinline__ void ldsm_x4(uint32_t* r, uint32_t addr) {
  asm volatile("ldmatrix.sync.aligned.m8n8.x4.shared.b16 {%0,%1,%2,%3}, [%4];"
               : "=r"(r[0]), "=r"(r[1]), "=r"(r[2]), "=r"(r[3]) : "r"(addr));
}
__device__ __forceinline__ void ldsm_x2(uint32_t* r, uint32_t addr) {
  asm volatile("ldmatrix.sync.aligned.m8n8.x2.shared.b16 {%0,%1}, [%2];"
               : "=r"(r[0]), "=r"(r[1]) : "r"(addr));
}
__device__ __forceinline__ void mma16816(float* d, const uint32_t* a, const uint32_t* b) {
  asm volatile(
      "mma.sync.aligned.m16n8k16.row.col.f32.bf16.bf16.f32 "
      "{%0,%1,%2,%3}, {%4,%5,%6,%7}, {%8,%9}, {%0,%1,%2,%3};"
      : "+f"(d[0]), "+f"(d[1]), "+f"(d[2]), "+f"(d[3])
      : "r"(a[0]), "r"(a[1]), "r"(a[2]), "r"(a[3]), "r"(b[0]), "r"(b[1]));
}

__device__ __forceinline__ uint32_t pack_bf2(__nv_bfloat16 a, __nv_bfloat16 b) {
  __nv_bfloat162 v(a, b);
  return *reinterpret_cast<uint32_t*>(&v);
}

__device__ __forceinline__ void split4(float4 a, uint2& vh, uint2& vl) {
  __nv_bfloat16 h0 = __float2bfloat16(a.x), h1 = __float2bfloat16(a.y);
  __nv_bfloat16 h2 = __float2bfloat16(a.z), h3 = __float2bfloat16(a.w);
  __nv_bfloat16 l0 = __float2bfloat16(a.x - __bfloat162float(h0));
  __nv_bfloat16 l1 = __float2bfloat16(a.y - __bfloat162float(h1));
  __nv_bfloat16 l2 = __float2bfloat16(a.z - __bfloat162float(h2));
  __nv_bfloat16 l3 = __float2bfloat16(a.w - __bfloat162float(h3));
  vh.x = pack_bf2(h0, h1); vh.y = pack_bf2(h2, h3);
  vl.x = pack_bf2(l0, l1); vl.y = pack_bf2(l2, l3);
}

// ---------------- fp32 -> bf16 hi/lo split (vectorized x4) ----------------
__global__ void k_convert4(const float* __restrict__ in,
                           __nv_bfloat16* __restrict__ hh,
                           __nv_bfloat16* __restrict__ hl, int n4) {
  int i = blockIdx.x * blockDim.x + threadIdx.x;
  if (i >= n4) return;
  float4 a = *(const float4*)(in + (size_t)i * 4);
  uint2 vh, vl;
  split4(a, vh, vl);
  *(uint2*)(hh + (size_t)i * 4) = vh;
  *(uint2*)(hl + (size_t)i * 4) = vl;
}

// ---------------- CSR build pipeline ----------------
__global__ void k_zero_i2(int* p, int* q, int n) {
  int i = blockIdx.x * blockDim.x + threadIdx.x;
  if (i < n) { p[i] = 0; q[i] = 0; }
}

__global__ void k_deg(const int* __restrict__ ei, int* __restrict__ deg) {
  int e = blockIdx.x * blockDim.x + threadIdx.x;
  if (e >= N_EDG) return;
  int col = ei[N_EDG + e];
  if ((unsigned)col < (unsigned)M_NODES) atomicAdd(&deg[col], 1);
}

__global__ void __launch_bounds__(1024)
k_scan1(const int* __restrict__ deg, int* __restrict__ rptr,
        int* __restrict__ bsum, float* __restrict__ dis) {
  __shared__ int sh[1024];
  int t = threadIdx.x;
  int idx = blockIdx.x * 1024 + t;
  int v = (idx < M_NODES) ? deg[idx] : 0;
  if (idx < M_NODES) dis[idx] = (v > 0) ? rsqrtf((float)v) : 0.0f;
  sh[t] = v;
  __syncthreads();
  int run = v;
  for (int off = 1; off < 1024; off <<= 1) {
    int u = (t >= off) ? sh[t - off] : 0;
    __syncthreads();
    run += u;
    sh[t] = run;
    __syncthreads();
  }
  if (idx < M_NODES) rptr[idx] = run - v;
  if (t == 1023) bsum[blockIdx.x] = run;
}

__global__ void __launch_bounds__(128)
k_scan2(const int* __restrict__ bsum, int* __restrict__ boff) {
  __shared__ int sh[SCAN_B];
  int t = threadIdx.x;
  if (t < SCAN_B) sh[t] = bsum[t];
  __syncthreads();
  if (t == 0) {
    int run = 0;
    for (int i = 0; i < SCAN_B; i++) {
      int v = sh[i];
      boff[i] = run;
      run += v;
    }
    boff[SCAN_B] = run;
  }
}

__global__ void __launch_bounds__(1024)
k_scan3(int* __restrict__ rptr, const int* __restrict__ boff) {
  int t = threadIdx.x;
  int idx = blockIdx.x * 1024 + t;
  if (idx < M_NODES) rptr[idx] += boff[blockIdx.x];
  if (idx == 0) rptr[M_NODES] = boff[SCAN_B];
}

__global__ void k_scatter(const int* __restrict__ ei, const float* __restrict__ dis,
                          const int* __restrict__ rptr, int* __restrict__ fill,
                          int* __restrict__ src, float* __restrict__ w) {
  int e = blockIdx.x * blockDim.x + threadIdx.x;
  if (e >= N_EDG) return;
  int row = ei[e];
  int col = ei[N_EDG + e];
  if ((unsigned)row >= (unsigned)M_NODES || (unsigned)col >= (unsigned)M_NODES) return;
  int pos = rptr[col] + atomicAdd(&fill[col], 1);
  src[pos] = row;
  w[pos] = dis[row] * dis[col];
}

// ---------------- CSR gather SpMM (unchanged winner) ----------------
template <int D>
__global__ void __launch_bounds__(128)
k_spmm_csr(float* __restrict__ out, const float* __restrict__ h,
           const int* __restrict__ rptr,
           const int* __restrict__ src,
           const float* __restrict__ w) {
  constexpr int TPN = D / 4;
  constexpr int NPB = 128 / TPN;
  int tid = threadIdx.x;
  int node = blockIdx.x * NPB + tid / TPN;
  if (node >= M_NODES) return;
  int c = (tid % TPN) * 4;
  int e0 = __ldg(&rptr[node]);
  int e1 = __ldg(&rptr[node + 1]);
  float4 acc = *(float4*)(out + (size_t)node * D + c);
  for (int e = e0; e < e1; e++) {
    int s = __ldg(&src[e]);
    float nm = __ldg(&w[e]);
    const float4 v = *(const float4*)(h + (size_t)s * D + c);
    acc.x = fmaf(nm, v.x, acc.x);
    acc.y = fmaf(nm, v.y, acc.y);
    acc.z = fmaf(nm, v.z, acc.z);
    acc.w = fmaf(nm, v.w, acc.w);
  }
  *(float4*)(out + (size_t)node * D + c) = acc;
}

// ---------------- tensor-core GEMM: pre-split bf16 inputs, warp mma.sync --------
// CTA: 128x64 C-tile of C[M, NTOT] = in[M,KTOT] @ Wcat[NTOT,KTOT]^T.
// grid = (ceil(M/128), NTOT/64). 128 threads, 2x2 warp grid, warp tile 64x32.
// Inputs are pre-split bf16 hi/lo (global); smem padded row-major copies.
// Accumulate Ah*Bh + Ah*Bl + Al*Bh in fp32 (3-product bf16 split).
template <int NOUT, int KTOT>
__global__ void __launch_bounds__(128)
k_gemm_mma(float* __restrict__ p0, float* __restrict__ p1,
           float* __restrict__ p2, float* __restrict__ p3,
           const __nv_bfloat16* __restrict__ inh, const __nv_bfloat16* __restrict__ inl,
           const __nv_bfloat16* __restrict__ Wh, const __nv_bfloat16* __restrict__ Wl,
           const float* __restrict__ bias) {
  extern __shared__ char smem[];
  constexpr int LDA = KTOT + 8;                   // bf16 elements per row (padded)
  constexpr size_t OFF_AH = 0;
  constexpr size_t OFF_AL = (size_t)128 * LDA * 2;
  constexpr size_t OFF_BH = 2 * OFF_AL;
  constexpr size_t OFF_BL = OFF_BH + (size_t)64 * LDA * 2;

  const int tid = threadIdx.x;
  const int lane = tid & 31, wid = tid >> 5;
  const int wm = (wid >> 1) * 64;
  const int wn = (wid & 1) * 32;
  const int m0 = blockIdx.x * 128;
  const int n0 = blockIdx.y * 64;

  // ---- A tile: straight bf16 copies (4 elems = 8B per iter) ----
  for (int i = tid; i < (128 * KTOT) / 4; i += 128) {
    int row = (i * 4) / KTOT, k = (i * 4) % KTOT;
    int m = m0 + row;
    uint2 vh = make_uint2(0u, 0u), vl = make_uint2(0u, 0u);
    if (m < M_NODES) {
      vh = *(const uint2*)(inh + (size_t)m * KTOT + k);
      vl = *(const uint2*)(inl + (size_t)m * KTOT + k);
    }
    size_t off = ((size_t)row * LDA + k) * 2;
    *(uint2*)(smem + OFF_AH + off) = vh;
    *(uint2*)(smem + OFF_AL + off) = vl;
  }

  // ---- B tile: 64 rows of Wcat ----
  for (int i = tid; i < (64 * KTOT) / 4; i += 128) {
    int row = (i * 4) / KTOT, k = (i * 4) % KTOT;
    size_t goff = (size_t)(n0 + row) * KTOT + k;
    uint2 vh = *(const uint2*)(Wh + goff);
    uint2 vl = *(const uint2*)(Wl + goff);
    size_t off = ((size_t)row * LDA + k) * 2;
    *(uint2*)(smem + OFF_BH + off) = vh;
    *(uint2*)(smem + OFF_BL + off) = vl;
  }
  __syncthreads();

  const uint32_t sb = smem_u32(smem);
  float acc[4][4][4];
#pragma unroll
  for (int mt = 0; mt < 4; mt++)
#pragma unroll
    for (int nt = 0; nt < 4; nt++)
#pragma unroll
      for (int f = 0; f < 4; f++) acc[mt][nt][f] = 0.0f;

  const int arow = wm + (lane & 15);
  const int acol = (lane >> 4) * 8;
  const int brow = wn + (lane & 7);
  const int bcol = ((lane >> 3) & 1) * 8;

  for (int k0 = 0; k0 < KTOT; k0 += 16) {
    uint32_t Ah[4][4], Al[4][4], Bh[4][2], Bl[4][2];
#pragma unroll
    for (int mt = 0; mt < 4; mt++) {
      uint32_t off = (uint32_t)(((arow + mt * 16) * LDA + k0 + acol) * 2);
      ldsm_x4(Ah[mt], sb + (uint32_t)OFF_AH + off);
      ldsm_x4(Al[mt], sb + (uint32_t)OFF_AL + off);
    }
#pragma unroll
    for (int nt = 0; nt < 4; nt++) {
      uint32_t off = (uint32_t)(((brow + nt * 8) * LDA + k0 + bcol) * 2);
      ldsm_x2(Bh[nt], sb + (uint32_t)OFF_BH + off);
      ldsm_x2(Bl[nt], sb + (uint32_t)OFF_BL + off);
    }
#pragma unroll
    for (int mt = 0; mt < 4; mt++)
#pragma unroll
      for (int nt = 0; nt < 4; nt++) {
        mma16816(acc[mt][nt], Ah[mt], Bh[nt]);
        mma16816(acc[mt][nt], Ah[mt], Bl[nt]);
        mma16816(acc[mt][nt], Al[mt], Bh[nt]);
      }
  }

#pragma unroll
  for (int mt = 0; mt < 4; mt++) {
    int gm0 = m0 + wm + mt * 16 + (lane >> 2);
#pragma unroll
    for (int nt = 0; nt < 4; nt++) {
      int gc = n0 + wn + nt * 8 + 2 * (lane & 3);
      int plane = gc / NOUT;
      int pc = gc % NOUT;
      float* op = (plane == 0) ? p0 : (plane == 1) ? p1 : (plane == 2) ? p2 : p3;
      float bx = 0.f, by = 0.f;
      if (plane == 0) { bx = bias[pc]; by = bias[pc + 1]; }
      if (gm0 < M_NODES) {
        float2 v0 = make_float2(acc[mt][nt][0] + bx, acc[mt][nt][1] + by);
        *(float2*)(op + (size_t)gm0 * NOUT + pc) = v0;
      }
      if (gm0 + 8 < M_NODES) {
        float2 v1 = make_float2(acc[mt][nt][2] + bx, acc[mt][nt][3] + by);
        *(float2*)(op + (size_t)(gm0 + 8) * NOUT + pc) = v1;
      }
    }
  }
}

// ---------------- dropout (+ optional ELU) fused with bf16 hi/lo split ----------
// Output feeds ONLY the next layer's GEMM -> write split bf16, skip fp32.
template <bool ELU>
__global__ void k_dropout_cv(const float* __restrict__ p,
                             __nv_bfloat16* __restrict__ hh,
                             __nv_bfloat16* __restrict__ hl,
                             int n, unsigned k0, unsigned k1) {
  int i = blockIdx.x * blockDim.x + threadIdx.x;
  if (i >= n) return;
  unsigned o0, o1;
  threefry2x32(k0, k1, 0u, (unsigned)i, o0, o1);
  unsigned bits = o0 ^ o1;
  float u = __uint_as_float((bits >> 9) | 0x3F800000u) - 1.0f;
  float v = p[i];
  if (ELU) v = (v > 0.0f) ? v : expm1f(v);
  v = (u < 0.5f) ? v * 2.0f : 0.0f;
  __nv_bfloat16 h = __float2bfloat16(v);
  __nv_bfloat16 l = __float2bfloat16(v - __bfloat162float(h));
  hh[i] = h;
  hl[i] = l;
}

// ---------------- host orchestration ----------------
static inline int cdiv(long long a, int b) { return (int)((a + b - 1) / b); }

extern "C" void kernel_launch(void* const* d_in, const int* in_sizes, int n_in,
                              void* d_out, int out_size) {
  const float* x  = (const float*)d_in[0];
  const int*   ei = (const int*)d_in[1];   // int32 (JAX x64 disabled)
  const float* W1 = (const float*)d_in[2];
  const float* b1 = (const float*)d_in[3];
  const float* W2 = (const float*)d_in[4];
  const float* b2 = (const float*)d_in[5];
  const float* W3 = (const float*)d_in[6];
  const float* b3 = (const float*)d_in[7];
  float* out = (float*)d_out;

  int *deg, *fill, *rptr, *srcv, *bsum, *boff;
  float *dis, *wv, *bA, *bB, *bC, *bD, *bE;
  __nv_bfloat16 *hh, *hl, *wh, *wl;
  cudaGetSymbolAddress((void**)&deg,  g_deg);
  cudaGetSymbolAddress((void**)&fill, g_fill);
  cudaGetSymbolAddress((void**)&rptr, g_rptr);
  cudaGetSymbolAddress((void**)&bsum, g_bsum);
  cudaGetSymbolAddress((void**)&boff, g_boff);
  cudaGetSymbolAddress((void**)&srcv, g_src);
  cudaGetSymbolAddress((void**)&wv,   g_w);
  cudaGetSymbolAddress((void**)&dis,  g_dis);
  cudaGetSymbolAddress((void**)&bA,   g_bufA);
  cudaGetSymbolAddress((void**)&bB,   g_bufB);
  cudaGetSymbolAddress((void**)&bC,   g_bufC);
  cudaGetSymbolAddress((void**)&bD,   g_bufD);
  cudaGetSymbolAddress((void**)&bE,   g_bufE);
  cudaGetSymbolAddress((void**)&hh,   g_hh);
  cudaGetSymbolAddress((void**)&hl,   g_hl);
  cudaGetSymbolAddress((void**)&wh,   g_wh);
  cudaGetSymbolAddress((void**)&wl,   g_wl);

  unsigned dk1a, dk1b, dk2a, dk2b;
  threefry2x32(0u, 42u, 0u, 0u, dk1a, dk1b);
  threefry2x32(0u, 42u, 0u, 1u, dk2a, dk2b);

  const int T = 256;
  const int GM = cdiv(M_NODES, 128);   // 782

  const int SM12 = 384 * (128 + 8) * 2;  // 104448 (KTOT=128)
  const int SM3  = 384 * (64 + 8) * 2;   // 55296  (KTOT=64)
  cudaFuncSetAttribute(k_gemm_mma<128, 128>, cudaFuncAttributeMaxDynamicSharedMemorySize, SM12);
  cudaFuncSetAttribute(k_gemm_mma<64, 128>,  cudaFuncAttributeMaxDynamicSharedMemorySize, SM12);
  cudaFuncSetAttribute(k_gemm_mma<16, 64>,   cudaFuncAttributeMaxDynamicSharedMemorySize, SM3);

  // ---- weight + input splits (once per launch) ----
  k_convert4<<<cdiv(65536 / 4, T), T>>>(W1, wh + WOFF1, wl + WOFF1, 65536 / 4);
  k_convert4<<<cdiv(32768 / 4, T), T>>>(W2, wh + WOFF2, wl + WOFF2, 32768 / 4);
  k_convert4<<<cdiv(4096 / 4,  T), T>>>(W3, wh + WOFF3, wl + WOFF3, 4096 / 4);
  k_convert4<<<cdiv((long long)M_NODES * 128 / 4, T), T>>>(x, hh, hl, M_NODES * 128 / 4);

  // ---- CSR build ----
  k_zero_i2<<<cdiv(M_NODES, T), T>>>(deg, fill, M_NODES);
  k_deg    <<<cdiv(N_EDG,   T), T>>>(ei, deg);
  k_scan1  <<<SCAN_B, 1024>>>(deg, rptr, bsum, dis);
  k_scan2  <<<1, 128>>>(bsum, boff);
  k_scan3  <<<SCAN_B, 1024>>>(rptr, boff);
  k_scatter<<<cdiv(N_EDG,   T), T>>>(ei, dis, rptr, fill, srcv, wv);

  // Horner per layer: P_k = h @ W_k^T; P2 += A P3; P1 += A P2; P0 += A P1.

  // ---- layer 1: 128 -> 128.  planes A(P0+b1), B, C, D ----
  {
    const int N = 128;
    k_gemm_mma<128, 128><<<dim3(GM, 8), 128, SM12>>>(bA, bB, bC, bD, hh, hl,
                                                     wh + WOFF1, wl + WOFF1, b1);
    const int NPB = 128 / (N / 4);
    k_spmm_csr<N><<<cdiv(M_NODES, NPB), 128>>>(bC, bD, rptr, srcv, wv);
    k_spmm_csr<N><<<cdiv(M_NODES, NPB), 128>>>(bB, bC, rptr, srcv, wv);
    k_spmm_csr<N><<<cdiv(M_NODES, NPB), 128>>>(bA, bB, rptr, srcv, wv);
    k_dropout_cv<false><<<cdiv((long long)M_NODES * N, T), T>>>(
        bA, hh, hl, M_NODES * N, dk1a, dk1b);
  }

  // ---- layer 2: 128 -> 64.  planes B(P0+b2), C, D, E ----
  {
    const int N = 64;
    k_gemm_mma<64, 128><<<dim3(GM, 4), 128, SM12>>>(bB, bC, bD, bE, hh, hl,
                                                    wh + WOFF2, wl + WOFF2, b2);
    const int NPB = 128 / (N / 4);
    k_spmm_csr<N><<<cdiv(M_NODES, NPB), 128>>>(bD, bE, rptr, srcv, wv);
    k_spmm_csr<N><<<cdiv(M_NODES, NPB), 128>>>(bC, bD, rptr, srcv, wv);
    k_spmm_csr<N><<<cdiv(M_NODES, NPB), 128>>>(bB, bC, rptr, srcv, wv);
    k_dropout_cv<true><<<cdiv((long long)M_NODES * N, T), T>>>(
        bB, hh, hl, M_NODES * N, dk2a, dk2b);
  }

  // ---- layer 3: 64 -> 16.  planes out(P0+b3), C, D, E ----
  {
    const int N = 16;
    k_gemm_mma<16, 64><<<dim3(GM, 1), 128, SM3>>>(out, bC, bD, bE, hh, hl,
                                                  wh + WOFF3, wl + WOFF3, b3);
    const int NPB = 128 / (N / 4);
    k_spmm_csr<N><<<cdiv(M_NODES, NPB), 128>>>(bD,  bE, rptr, srcv, wv);
    k_spmm_csr<N><<<cdiv(M_NODES, NPB), 128>>>(bC,  bD, rptr, srcv, wv);
    k_spmm_csr<N><<<cdiv(M_NODES, NPB), 128>>>(out, bC, rptr, srcv, wv);
  }
}

// round 17
// speedup vs baseline: 1.2595x; 1.2595x over previous
#include <cuda_runtime.h>
#include <cuda_bf16.h>
#include <cstdint>
#include <cstddef>

#define M_NODES 100000
#define N_EDG   1600000
#define SCAN_B 98   // ceil(M_NODES / 1024)

// ---------------- scratch (static device globals; no allocation) ----------------
__device__ int   g_deg[M_NODES];
__device__ int   g_fill[M_NODES];
__device__ int   g_rptr[M_NODES + 1];
__device__ int   g_bsum[SCAN_B];
__device__ int   g_boff[SCAN_B + 1];
__device__ int   g_src[N_EDG];
__device__ float g_w[N_EDG];
__device__ float g_dis[M_NODES];
__device__ __align__(16) float g_bufA[(size_t)M_NODES * 128];
__device__ __align__(16) float g_bufB[(size_t)M_NODES * 128];
__device__ __align__(16) float g_bufC[(size_t)M_NODES * 128];
__device__ __align__(16) float g_bufD[(size_t)M_NODES * 128];
__device__ __align__(16) float g_bufE[(size_t)M_NODES * 128];
// bf16 hi/lo split buffers: GEMM input activations + all weights
__device__ __align__(16) __nv_bfloat16 g_hh[(size_t)M_NODES * 128];
__device__ __align__(16) __nv_bfloat16 g_hl[(size_t)M_NODES * 128];
#define WOFF1 0
#define WOFF2 65536            // 4*128*128
#define WOFF3 98304            // + 4*64*128
#define WTOT  102400           // + 4*16*64
__device__ __align__(16) __nv_bfloat16 g_wh[WTOT];
__device__ __align__(16) __nv_bfloat16 g_wl[WTOT];

// ---------------- threefry2x32 ----------------
__host__ __device__ __forceinline__ unsigned tf_rotl(unsigned x, int r) {
  return (x << r) | (x >> (32 - r));
}

__host__ __device__ __forceinline__ void threefry2x32(
    unsigned k0, unsigned k1, unsigned x0, unsigned x1,
    unsigned& o0, unsigned& o1) {
  unsigned ks2 = k0 ^ k1 ^ 0x1BD11BDAu;
  x0 += k0; x1 += k1;
#define TF_R(r) { x0 += x1; x1 = tf_rotl(x1, (r)); x1 ^= x0; }
  TF_R(13) TF_R(15) TF_R(26) TF_R(6)
  x0 += k1;  x1 += ks2 + 1u;
  TF_R(17) TF_R(29) TF_R(16) TF_R(24)
  x0 += ks2; x1 += k0 + 2u;
  TF_R(13) TF_R(15) TF_R(26) TF_R(6)
  x0 += k0;  x1 += k1 + 3u;
  TF_R(17) TF_R(29) TF_R(16) TF_R(24)
  x0 += k1;  x1 += ks2 + 4u;
  TF_R(13) TF_R(15) TF_R(26) TF_R(6)
  x0 += ks2; x1 += k0 + 5u;
#undef TF_R
  o0 = x0; o1 = x1;
}

// ---------------- warp-MMA helpers (baseline PTX, no 'a'-gated features) --------
__device__ __forceinline__ uint32_t smem_u32(const void* p) {
  uint32_t a;
  asm("{ .reg .u64 t; cvta.to.shared.u64 t, %1; cvt.u32.u64 %0, t; }"
      : "=r"(a) : "l"(p));
  return a;
}

__device__ __forceinline__ void ldsm_x4(uint32_t* r, uint32_t addr) {
  asm volatile("ldmatrix.sync.aligned.m8n8.x4.shared.b16 {%0,%1,%2,%3}, [%4];"
               : "=r"(r[0]), "=r"(r[1]), "=r"(r[2]), "=r"(r[3]) : "r"(addr));
}
__device__ __forceinline__ void ldsm_x2(uint32_t* r, uint32_t addr) {
  asm volatile("ldmatrix.sync.aligned.m8n8.x2.shared.b16 {%0,%1}, [%2];"
               : "=r"(r[0]), "=r"(r[1]) : "r"(addr));
}
__device__ __forceinline__ void mma16816(float* d, const uint32_t* a, const uint32_t* b) {
  asm volatile(
      "mma.sync.aligned.m16n8k16.row.col.f32.bf16.bf16.f32 "
      "{%0,%1,%2,%3}, {%4,%5,%6,%7}, {%8,%9}, {%0,%1,%2,%3};"
      : "+f"(d[0]), "+f"(d[1]), "+f"(d[2]), "+f"(d[3])
      : "r"(a[0]), "r"(a[1]), "r"(a[2]), "r"(a[3]), "r"(b[0]), "r"(b[1]));
}

__device__ __forceinline__ uint32_t pack_bf2(__nv_bfloat16 a, __nv_bfloat16 b) {
  __nv_bfloat162 v(a, b);
  return *reinterpret_cast<uint32_t*>(&v);
}

__device__ __forceinline__ void split4(float4 a, uint2& vh, uint2& vl) {
  __nv_bfloat16 h0 = __float2bfloat16(a.x), h1 = __float2bfloat16(a.y);
  __nv_bfloat16 h2 = __float2bfloat16(a.z), h3 = __float2bfloat16(a.w);
  __nv_bfloat16 l0 = __float2bfloat16(a.x - __bfloat162float(h0));
  __nv_bfloat16 l1 = __float2bfloat16(a.y - __bfloat162float(h1));
  __nv_bfloat16 l2 = __float2bfloat16(a.z - __bfloat162float(h2));
  __nv_bfloat16 l3 = __float2bfloat16(a.w - __bfloat162float(h3));
  vh.x = pack_bf2(h0, h1); vh.y = pack_bf2(h2, h3);
  vl.x = pack_bf2(l0, l1); vl.y = pack_bf2(l2, l3);
}

// ---------------- fp32 -> bf16 hi/lo split (vectorized x4) ----------------
__global__ void k_convert4(const float* __restrict__ in,
                           __nv_bfloat16* __restrict__ hh,
                           __nv_bfloat16* __restrict__ hl, int n4) {
  int i = blockIdx.x * blockDim.x + threadIdx.x;
  if (i >= n4) return;
  float4 a = *(const float4*)(in + (size_t)i * 4);
  uint2 vh, vl;
  split4(a, vh, vl);
  *(uint2*)(hh + (size_t)i * 4) = vh;
  *(uint2*)(hl + (size_t)i * 4) = vl;
}

// ---------------- CSR build pipeline ----------------
__global__ void k_zero_i2(int* p, int* q, int n) {
  int i = blockIdx.x * blockDim.x + threadIdx.x;
  if (i < n) { p[i] = 0; q[i] = 0; }
}

__global__ void k_deg(const int* __restrict__ ei, int* __restrict__ deg) {
  int e = blockIdx.x * blockDim.x + threadIdx.x;
  if (e >= N_EDG) return;
  int col = ei[N_EDG + e];
  if ((unsigned)col < (unsigned)M_NODES) atomicAdd(&deg[col], 1);
}

__global__ void __launch_bounds__(1024)
k_scan1(const int* __restrict__ deg, int* __restrict__ rptr,
        int* __restrict__ bsum, float* __restrict__ dis) {
  __shared__ int sh[1024];
  int t = threadIdx.x;
  int idx = blockIdx.x * 1024 + t;
  int v = (idx < M_NODES) ? deg[idx] : 0;
  if (idx < M_NODES) dis[idx] = (v > 0) ? rsqrtf((float)v) : 0.0f;
  sh[t] = v;
  __syncthreads();
  int run = v;
  for (int off = 1; off < 1024; off <<= 1) {
    int u = (t >= off) ? sh[t - off] : 0;
    __syncthreads();
    run += u;
    sh[t] = run;
    __syncthreads();
  }
  if (idx < M_NODES) rptr[idx] = run - v;
  if (t == 1023) bsum[blockIdx.x] = run;
}

__global__ void __launch_bounds__(128)
k_scan2(const int* __restrict__ bsum, int* __restrict__ boff) {
  __shared__ int sh[SCAN_B];
  int t = threadIdx.x;
  if (t < SCAN_B) sh[t] = bsum[t];
  __syncthreads();
  if (t == 0) {
    int run = 0;
    for (int i = 0; i < SCAN_B; i++) {
      int v = sh[i];
      boff[i] = run;
      run += v;
    }
    boff[SCAN_B] = run;
  }
}

__global__ void __launch_bounds__(1024)
k_scan3(int* __restrict__ rptr, const int* __restrict__ boff) {
  int t = threadIdx.x;
  int idx = blockIdx.x * 1024 + t;
  if (idx < M_NODES) rptr[idx] += boff[blockIdx.x];
  if (idx == 0) rptr[M_NODES] = boff[SCAN_B];
}

__global__ void k_scatter(const int* __restrict__ ei, const float* __restrict__ dis,
                          const int* __restrict__ rptr, int* __restrict__ fill,
                          int* __restrict__ src, float* __restrict__ w) {
  int e = blockIdx.x * blockDim.x + threadIdx.x;
  if (e >= N_EDG) return;
  int row = ei[e];
  int col = ei[N_EDG + e];
  if ((unsigned)row >= (unsigned)M_NODES || (unsigned)col >= (unsigned)M_NODES) return;
  int pos = rptr[col] + atomicAdd(&fill[col], 1);
  src[pos] = row;
  w[pos] = dis[row] * dis[col];
}

// ---------------- CSR gather SpMM (unchanged winner) ----------------
template <int D>
__global__ void __launch_bounds__(128)
k_spmm_csr(float* __restrict__ out, const float* __restrict__ h,
           const int* __restrict__ rptr,
           const int* __restrict__ src,
           const float* __restrict__ w) {
  constexpr int TPN = D / 4;
  constexpr int NPB = 128 / TPN;
  int tid = threadIdx.x;
  int node = blockIdx.x * NPB + tid / TPN;
  if (node >= M_NODES) return;
  int c = (tid % TPN) * 4;
  int e0 = __ldg(&rptr[node]);
  int e1 = __ldg(&rptr[node + 1]);
  float4 acc = *(float4*)(out + (size_t)node * D + c);
  for (int e = e0; e < e1; e++) {
    int s = __ldg(&src[e]);
    float nm = __ldg(&w[e]);
    const float4 v = *(const float4*)(h + (size_t)s * D + c);
    acc.x = fmaf(nm, v.x, acc.x);
    acc.y = fmaf(nm, v.y, acc.y);
    acc.z = fmaf(nm, v.z, acc.z);
    acc.w = fmaf(nm, v.w, acc.w);
  }
  *(float4*)(out + (size_t)node * D + c) = acc;
}

// ---------------- tensor-core GEMM v2: k-tiled, 256 threads, 16 warps/SM --------
// CTA: 128 x BN C-tile of C[M, NTOT] = in[M,KTOT] @ Wcat[NTOT,KTOT]^T.
// grid = (ceil(M/128), NTOT/BN). 8 warps: BN=128 -> 2x4 grid (warp 64x32);
// BN=64 -> 4x2 grid (warp 32x32). BK=64 k-tiles in padded smem.
// Accumulate Ah*Bh + Ah*Bl + Al*Bh in fp32 (3-product bf16 split).
template <int NOUT, int KTOT, int BN>
__global__ void __launch_bounds__(256, 2)
k_gemm_mma2(float* __restrict__ p0, float* __restrict__ p1,
            float* __restrict__ p2, float* __restrict__ p3,
            const __nv_bfloat16* __restrict__ inh, const __nv_bfloat16* __restrict__ inl,
            const __nv_bfloat16* __restrict__ Wh, const __nv_bfloat16* __restrict__ Wl,
            const float* __restrict__ bias) {
  extern __shared__ char smem[];
  constexpr int BK = 64;
  constexpr int LD = BK + 8;                  // padded row length (bf16 elems)
  constexpr size_t OFF_AH = 0;
  constexpr size_t OFF_AL = (size_t)128 * LD * 2;
  constexpr size_t OFF_BH = 2 * OFF_AL;
  constexpr size_t OFF_BL = OFF_BH + (size_t)BN * LD * 2;
  constexpr int WGN = BN / 32;                // warps along n
  constexpr int WGM = 8 / WGN;                // warps along m
  constexpr int MT  = (128 / WGM) / 16;       // m16 steps per warp

  const int tid = threadIdx.x;
  const int lane = tid & 31, wid = tid >> 5;
  const int wm = (wid / WGN) * (128 / WGM);
  const int wn = (wid % WGN) * 32;
  const int m0 = blockIdx.x * 128;
  const int n0 = blockIdx.y * BN;

  const uint32_t sb = smem_u32(smem);
  float acc[MT][4][4];
#pragma unroll
  for (int mt = 0; mt < MT; mt++)
#pragma unroll
    for (int nt = 0; nt < 4; nt++)
#pragma unroll
      for (int f = 0; f < 4; f++) acc[mt][nt][f] = 0.0f;

  const int arow = wm + (lane & 15);
  const int acol = (lane >> 4) * 8;
  const int brow = wn + (lane & 7);
  const int bcol = ((lane >> 3) & 1) * 8;

  for (int kt = 0; kt < KTOT; kt += BK) {
    __syncthreads();   // previous tile fully consumed
    // A tile: 128 x BK hi+lo (4 bf16 per 8B iter)
    for (int i = tid; i < (128 * BK) / 4; i += 256) {
      int row = (i * 4) / BK, k = (i * 4) % BK;
      int m = m0 + row;
      uint2 vh = make_uint2(0u, 0u), vl = make_uint2(0u, 0u);
      if (m < M_NODES) {
        vh = *(const uint2*)(inh + (size_t)m * KTOT + kt + k);
        vl = *(const uint2*)(inl + (size_t)m * KTOT + kt + k);
      }
      size_t off = ((size_t)row * LD + k) * 2;
      *(uint2*)(smem + OFF_AH + off) = vh;
      *(uint2*)(smem + OFF_AL + off) = vl;
    }
    // B tile: BN x BK hi+lo
    for (int i = tid; i < (BN * BK) / 4; i += 256) {
      int row = (i * 4) / BK, k = (i * 4) % BK;
      size_t goff = (size_t)(n0 + row) * KTOT + kt + k;
      uint2 vh = *(const uint2*)(Wh + goff);
      uint2 vl = *(const uint2*)(Wl + goff);
      size_t off = ((size_t)row * LD + k) * 2;
      *(uint2*)(smem + OFF_BH + off) = vh;
      *(uint2*)(smem + OFF_BL + off) = vl;
    }
    __syncthreads();

#pragma unroll
    for (int ks = 0; ks < BK; ks += 16) {
      uint32_t Ah[MT][4], Al[MT][4], Bh[4][2], Bl[4][2];
#pragma unroll
      for (int mt = 0; mt < MT; mt++) {
        uint32_t off = (uint32_t)(((arow + mt * 16) * LD + ks + acol) * 2);
        ldsm_x4(Ah[mt], sb + (uint32_t)OFF_AH + off);
        ldsm_x4(Al[mt], sb + (uint32_t)OFF_AL + off);
      }
#pragma unroll
      for (int nt = 0; nt < 4; nt++) {
        uint32_t off = (uint32_t)(((brow + nt * 8) * LD + ks + bcol) * 2);
        ldsm_x2(Bh[nt], sb + (uint32_t)OFF_BH + off);
        ldsm_x2(Bl[nt], sb + (uint32_t)OFF_BL + off);
      }
#pragma unroll
      for (int mt = 0; mt < MT; mt++)
#pragma unroll
        for (int nt = 0; nt < 4; nt++) {
          mma16816(acc[mt][nt], Ah[mt], Bh[nt]);
          mma16816(acc[mt][nt], Ah[mt], Bl[nt]);
          mma16816(acc[mt][nt], Al[mt], Bh[nt]);
        }
    }
  }

  // ---- epilogue: fragment (c0,c1)=row lane/4, cols 2(lane%4); (c2,c3)=row+8 ----
#pragma unroll
  for (int mt = 0; mt < MT; mt++) {
    int gm0 = m0 + wm + mt * 16 + (lane >> 2);
#pragma unroll
    for (int nt = 0; nt < 4; nt++) {
      int gc = n0 + wn + nt * 8 + 2 * (lane & 3);
      int plane = gc / NOUT;
      int pc = gc % NOUT;
      float* op = (plane == 0) ? p0 : (plane == 1) ? p1 : (plane == 2) ? p2 : p3;
      float bx = 0.f, by = 0.f;
      if (plane == 0) { bx = bias[pc]; by = bias[pc + 1]; }
      if (gm0 < M_NODES) {
        float2 v0 = make_float2(acc[mt][nt][0] + bx, acc[mt][nt][1] + by);
        *(float2*)(op + (size_t)gm0 * NOUT + pc) = v0;
      }
      if (gm0 + 8 < M_NODES) {
        float2 v1 = make_float2(acc[mt][nt][2] + bx, acc[mt][nt][3] + by);
        *(float2*)(op + (size_t)(gm0 + 8) * NOUT + pc) = v1;
      }
    }
  }
}

// ---------------- dropout (+ optional ELU) fused with bf16 hi/lo split ----------
template <bool ELU>
__global__ void k_dropout_cv(const float* __restrict__ p,
                             __nv_bfloat16* __restrict__ hh,
                             __nv_bfloat16* __restrict__ hl,
                             int n, unsigned k0, unsigned k1) {
  int i = blockIdx.x * blockDim.x + threadIdx.x;
  if (i >= n) return;
  unsigned o0, o1;
  threefry2x32(k0, k1, 0u, (unsigned)i, o0, o1);
  unsigned bits = o0 ^ o1;
  float u = __uint_as_float((bits >> 9) | 0x3F800000u) - 1.0f;
  float v = p[i];
  if (ELU) v = (v > 0.0f) ? v : expm1f(v);
  v = (u < 0.5f) ? v * 2.0f : 0.0f;
  __nv_bfloat16 h = __float2bfloat16(v);
  __nv_bfloat16 l = __float2bfloat16(v - __bfloat162float(h));
  hh[i] = h;
  hl[i] = l;
}

// ---------------- host orchestration ----------------
static inline int cdiv(long long a, int b) { return (int)((a + b - 1) / b); }

extern "C" void kernel_launch(void* const* d_in, const int* in_sizes, int n_in,
                              void* d_out, int out_size) {
  const float* x  = (const float*)d_in[0];
  const int*   ei = (const int*)d_in[1];   // int32 (JAX x64 disabled)
  const float* W1 = (const float*)d_in[2];
  const float* b1 = (const float*)d_in[3];
  const float* W2 = (const float*)d_in[4];
  const float* b2 = (const float*)d_in[5];
  const float* W3 = (const float*)d_in[6];
  const float* b3 = (const float*)d_in[7];
  float* out = (float*)d_out;

  int *deg, *fill, *rptr, *srcv, *bsum, *boff;
  float *dis, *wv, *bA, *bB, *bC, *bD, *bE;
  __nv_bfloat16 *hh, *hl, *wh, *wl;
  cudaGetSymbolAddress((void**)&deg,  g_deg);
  cudaGetSymbolAddress((void**)&fill, g_fill);
  cudaGetSymbolAddress((void**)&rptr, g_rptr);
  cudaGetSymbolAddress((void**)&bsum, g_bsum);
  cudaGetSymbolAddress((void**)&boff, g_boff);
  cudaGetSymbolAddress((void**)&srcv, g_src);
  cudaGetSymbolAddress((void**)&wv,   g_w);
  cudaGetSymbolAddress((void**)&dis,  g_dis);
  cudaGetSymbolAddress((void**)&bA,   g_bufA);
  cudaGetSymbolAddress((void**)&bB,   g_bufB);
  cudaGetSymbolAddress((void**)&bC,   g_bufC);
  cudaGetSymbolAddress((void**)&bD,   g_bufD);
  cudaGetSymbolAddress((void**)&bE,   g_bufE);
  cudaGetSymbolAddress((void**)&hh,   g_hh);
  cudaGetSymbolAddress((void**)&hl,   g_hl);
  cudaGetSymbolAddress((void**)&wh,   g_wh);
  cudaGetSymbolAddress((void**)&wl,   g_wl);

  unsigned dk1a, dk1b, dk2a, dk2b;
  threefry2x32(0u, 42u, 0u, 0u, dk1a, dk1b);
  threefry2x32(0u, 42u, 0u, 1u, dk2a, dk2b);

  const int T = 256;
  const int GM = cdiv(M_NODES, 128);   // 782

  // dynamic smem: (128 + BN) rows * (64+8) bf16 * 2 (hi/lo)
  const int SMB128 = (128 + 128) * 72 * 2 * 2;  // 73728
  const int SMB64  = (128 + 64)  * 72 * 2 * 2;  // 55296
  cudaFuncSetAttribute(k_gemm_mma2<128, 128, 128>, cudaFuncAttributeMaxDynamicSharedMemorySize, SMB128);
  cudaFuncSetAttribute(k_gemm_mma2<64, 128, 128>,  cudaFuncAttributeMaxDynamicSharedMemorySize, SMB128);
  cudaFuncSetAttribute(k_gemm_mma2<16, 64, 64>,    cudaFuncAttributeMaxDynamicSharedMemorySize, SMB64);

  // ---- weight + input splits (once per launch) ----
  k_convert4<<<cdiv(65536 / 4, T), T>>>(W1, wh + WOFF1, wl + WOFF1, 65536 / 4);
  k_convert4<<<cdiv(32768 / 4, T), T>>>(W2, wh + WOFF2, wl + WOFF2, 32768 / 4);
  k_convert4<<<cdiv(4096 / 4,  T), T>>>(W3, wh + WOFF3, wl + WOFF3, 4096 / 4);
  k_convert4<<<cdiv((long long)M_NODES * 128 / 4, T), T>>>(x, hh, hl, M_NODES * 128 / 4);

  // ---- CSR build ----
  k_zero_i2<<<cdiv(M_NODES, T), T>>>(deg, fill, M_NODES);
  k_deg    <<<cdiv(N_EDG,   T), T>>>(ei, deg);
  k_scan1  <<<SCAN_B, 1024>>>(deg, rptr, bsum, dis);
  k_scan2  <<<1, 128>>>(bsum, boff);
  k_scan3  <<<SCAN_B, 1024>>>(rptr, boff);
  k_scatter<<<cdiv(N_EDG,   T), T>>>(ei, dis, rptr, fill, srcv, wv);

  // Horner per layer: P_k = h @ W_k^T; P2 += A P3; P1 += A P2; P0 += A P1.

  // ---- layer 1: 128 -> 128.  planes A(P0+b1), B, C, D ----
  {
    const int N = 128;
    k_gemm_mma2<128, 128, 128><<<dim3(GM, 4), 256, SMB128>>>(
        bA, bB, bC, bD, hh, hl, wh + WOFF1, wl + WOFF1, b1);
    const int NPB = 128 / (N / 4);
    k_spmm_csr<N><<<cdiv(M_NODES, NPB), 128>>>(bC, bD, rptr, srcv, wv);
    k_spmm_csr<N><<<cdiv(M_NODES, NPB), 128>>>(bB, bC, rptr, srcv, wv);
    k_spmm_csr<N><<<cdiv(M_NODES, NPB), 128>>>(bA, bB, rptr, srcv, wv);
    k_dropout_cv<false><<<cdiv((long long)M_NODES * N, T), T>>>(
        bA, hh, hl, M_NODES * N, dk1a, dk1b);
  }

  // ---- layer 2: 128 -> 64.  planes B(P0+b2), C, D, E ----
  {
    const int N = 64;
    k_gemm_mma2<64, 128, 128><<<dim3(GM, 2), 256, SMB128>>>(
        bB, bC, bD, bE, hh, hl, wh + WOFF2, wl + WOFF2, b2);
    const int NPB = 128 / (N / 4);
    k_spmm_csr<N><<<cdiv(M_NODES, NPB), 128>>>(bD, bE, rptr, srcv, wv);
    k_spmm_csr<N><<<cdiv(M_NODES, NPB), 128>>>(bC, bD, rptr, srcv, wv);
    k_spmm_csr<N><<<cdiv(M_NODES, NPB), 128>>>(bB, bC, rptr, srcv, wv);
    k_dropout_cv<true><<<cdiv((long long)M_NODES * N, T), T>>>(
        bB, hh, hl, M_NODES * N, dk2a, dk2b);
  }

  // ---- layer 3: 64 -> 16.  planes out(P0+b3), C, D, E ----
  {
    const int N = 16;
    k_gemm_mma2<16, 64, 64><<<dim3(GM, 1), 256, SMB64>>>(
        out, bC, bD, bE, hh, hl, wh + WOFF3, wl + WOFF3, b3);
    const int NPB = 128 / (N / 4);
    k_spmm_csr<N><<<cdiv(M_NODES, NPB), 128>>>(bD,  bE, rptr, srcv, wv);
    k_spmm_csr<N><<<cdiv(M_NODES, NPB), 128>>>(bC,  bD, rptr, srcv, wv);
    k_spmm_csr<N><<<cdiv(M_NODES, NPB), 128>>>(out, bC, rptr, srcv, wv);
  }
}